// round 2
// baseline (speedup 1.0000x reference)
#include <cuda_runtime.h>
#include <math.h>

#define NB 256   // batch
#define TT 64    // encoder time steps
#define HH 1024  // hidden
#define FH 4096  // 4*hidden
#define VV 128   // vocab
#define LL 32    // decode steps

typedef unsigned long long u64;

// ---------------- scratch (static device globals; no runtime allocation) ----
__device__ float g_encXW[VV * FH];   // enc_emb @ enc_W + enc_b
__device__ float g_decXW[VV * FH];   // dec_emb @ dec_W + dec_b
__device__ float g_h[2][NB * HH];
__device__ float g_c[2][NB * HH];
__device__ int   g_tok[2][NB];

__device__ __forceinline__ float sigm(float x) { return 1.0f / (1.0f + expf(-x)); }

// packed fp32 FMA: d = a*b + d elementwise on two packed f32 (Blackwell FFMA2)
__device__ __forceinline__ void fma2(u64 &d, const u64 a, const u64 b) {
    asm("fma.rn.f32x2 %0, %1, %2, %0;" : "+l"(d) : "l"(a), "l"(b));
}
__device__ __forceinline__ float2 u2f2(u64 v) {
    float2 r;
    asm("mov.b64 {%0, %1}, %2;" : "=f"(r.x), "=f"(r.y) : "l"(v));
    return r;
}

// ---------------- init: zero h0/c0, tok0 = delimiter -----------------------
__global__ void init_kernel() {
    int idx = blockIdx.x * blockDim.x + threadIdx.x;
    if (idx < NB * HH) { g_h[0][idx] = 0.0f; g_c[0][idx] = 0.0f; }
    if (idx < NB)      { g_tok[0][idx] = VV - 1; }
}

// ---------------- table precompute: tab[v][n] = emb[v,:] @ W[:,n] + b[n] ----
// grid (FH/128, 128/64, 2), 128 threads. BM=64, BN=128, BK=16, TM=TN=8.
__global__ void __launch_bounds__(128) table_kernel(
    const float* __restrict__ eemb, const float* __restrict__ eW, const float* __restrict__ eb,
    const float* __restrict__ demb, const float* __restrict__ dW, const float* __restrict__ db)
{
    const float* A; const float* W; const float* bias; float* out;
    if (blockIdx.z == 0) { A = eemb; W = eW; bias = eb; out = g_encXW; }
    else                 { A = demb; W = dW; bias = db; out = g_decXW; }

    __shared__ float As[16][64];
    __shared__ float Bs[16][128];

    const int n0 = blockIdx.x * 128;
    const int m0 = blockIdx.y * 64;
    const int tid = threadIdx.x;

    const int am = tid >> 1, ak = (tid & 1) * 8;     // A: 64x16, 8 floats/thread
    const int bk = tid >> 3, bc = (tid & 7) * 16;    // B: 16x128, 16 floats/thread
    const int ty = tid >> 4, tx = tid & 15;

    float acc[8][8];
#pragma unroll
    for (int i = 0; i < 8; i++)
#pragma unroll
        for (int j = 0; j < 8; j++) acc[i][j] = 0.0f;

    const float* Ap = A + (size_t)(m0 + am) * HH + ak;
    const float* Bp = W + (size_t)bk * FH + n0 + bc;

    float4 ap0 = *(const float4*)(Ap);
    float4 ap1 = *(const float4*)(Ap + 4);
    float4 bp0 = *(const float4*)(Bp);
    float4 bp1 = *(const float4*)(Bp + 4);
    float4 bp2 = *(const float4*)(Bp + 8);
    float4 bp3 = *(const float4*)(Bp + 12);

    const int NKT = HH / 16;
    for (int kt = 0; kt < NKT; ++kt) {
        As[ak + 0][am] = ap0.x; As[ak + 1][am] = ap0.y; As[ak + 2][am] = ap0.z; As[ak + 3][am] = ap0.w;
        As[ak + 4][am] = ap1.x; As[ak + 5][am] = ap1.y; As[ak + 6][am] = ap1.z; As[ak + 7][am] = ap1.w;
        *(float4*)&Bs[bk][bc]      = bp0;
        *(float4*)&Bs[bk][bc + 4]  = bp1;
        *(float4*)&Bs[bk][bc + 8]  = bp2;
        *(float4*)&Bs[bk][bc + 12] = bp3;
        __syncthreads();
        if (kt + 1 < NKT) {
            const float* a2 = Ap + (kt + 1) * 16;
            const float* b2 = Bp + (size_t)(kt + 1) * 16 * FH;
            ap0 = *(const float4*)a2; ap1 = *(const float4*)(a2 + 4);
            bp0 = *(const float4*)b2; bp1 = *(const float4*)(b2 + 4);
            bp2 = *(const float4*)(b2 + 8); bp3 = *(const float4*)(b2 + 12);
        }
#pragma unroll
        for (int k = 0; k < 16; k++) {
            float4 av0 = *(const float4*)&As[k][ty * 8];
            float4 av1 = *(const float4*)&As[k][ty * 8 + 4];
            float4 bv0 = *(const float4*)&Bs[k][tx * 8];
            float4 bv1 = *(const float4*)&Bs[k][tx * 8 + 4];
            float a[8] = {av0.x, av0.y, av0.z, av0.w, av1.x, av1.y, av1.z, av1.w};
            float b[8] = {bv0.x, bv0.y, bv0.z, bv0.w, bv1.x, bv1.y, bv1.z, bv1.w};
#pragma unroll
            for (int i = 0; i < 8; i++)
#pragma unroll
                for (int j = 0; j < 8; j++) acc[i][j] = fmaf(a[i], b[j], acc[i][j]);
        }
        __syncthreads();
    }
#pragma unroll
    for (int i = 0; i < 8; i++) {
        int m = m0 + ty * 8 + i;
#pragma unroll
        for (int j = 0; j < 8; j++) {
            int n = n0 + tx * 8 + j;
            out[(size_t)m * FH + n] = acc[i][j] + bias[n];
        }
    }
}

// ---------------- fused LSTM step (FFMA2 version) --------------------------
// z = xW[tok] + h_in @ U ; gates ; masked h/c update.
// Block: 64(batch) x 32(col-per-gate) tile, all 4 gates. 256 threads, 8 warps.
// Internal BN=128 cols: col -> global n = (col>>5)*HH + n0 + (col&31).
// A stored DUPLICATED in smem ({a,a} pairs) so the inner loop is pure
// ulonglong2 LDS + fma.rn.f32x2 (packed fp32, 2 FMA/lane/instr).
// grid (HH/32=32, NB/64=4) = 128 blocks.
__global__ void __launch_bounds__(256) lstm_step_kernel(
    const float* __restrict__ U, int isDec,
    const int* __restrict__ tokExt, int tokStride,
    int pin, int pout, int tokPing)
{
    const float* xW   = isDec ? g_decXW : g_encXW;
    const int*   tok  = isDec ? g_tok[tokPing] : tokExt;
    const float* h_in = g_h[pin];
    const float* c_in = g_c[pin];
    float* h_out = g_h[pout];
    float* c_out = g_c[pout];

    __shared__ union {
        struct { float Ad[16][128]; float Bs[16][128]; } g;  // 16 KB during GEMM
        float Zt[64][132];                                    // 33.8 KB after
    } sm;

    const int n0 = blockIdx.x * 32;
    const int b0 = blockIdx.y * 64;
    const int tid = threadIdx.x;

    const int am = tid >> 2, ak = (tid & 3) * 4;   // A tile 64x16: 1 float4/thread
    const int bk = tid >> 4, bc = (tid & 15) * 8;  // B tile 16x128: 2 float4/thread
    const int ty = tid >> 4, tx = tid & 15;        // compute: 4m x 8n per thread

    u64 acc[4][4];
#pragma unroll
    for (int i = 0; i < 4; i++)
#pragma unroll
        for (int j = 0; j < 4; j++) acc[i][j] = 0ULL;

    const int bgate = bc >> 5;
    const int bj    = bc & 31;
    const float* Ap = h_in + (size_t)(b0 + am) * HH + ak;
    const float* Bp = U + (size_t)bk * FH + (size_t)bgate * HH + n0 + bj;

    float4 apre  = *(const float4*)(Ap);
    float4 bpre0 = *(const float4*)(Bp);
    float4 bpre1 = *(const float4*)(Bp + 4);

    const int NKT = HH / 16;
    for (int kt = 0; kt < NKT; ++kt) {
        // store A duplicated: Ad[k][2m] = Ad[k][2m+1] = h[b0+m][k]
        *(float2*)&sm.g.Ad[ak + 0][2 * am] = make_float2(apre.x, apre.x);
        *(float2*)&sm.g.Ad[ak + 1][2 * am] = make_float2(apre.y, apre.y);
        *(float2*)&sm.g.Ad[ak + 2][2 * am] = make_float2(apre.z, apre.z);
        *(float2*)&sm.g.Ad[ak + 3][2 * am] = make_float2(apre.w, apre.w);
        *(float4*)&sm.g.Bs[bk][bc]     = bpre0;
        *(float4*)&sm.g.Bs[bk][bc + 4] = bpre1;
        __syncthreads();
        if (kt + 1 < NKT) {
            apre = *(const float4*)(Ap + (kt + 1) * 16);
            const float* b2 = Bp + (size_t)(kt + 1) * 16 * FH;
            bpre0 = *(const float4*)b2;
            bpre1 = *(const float4*)(b2 + 4);
        }
#pragma unroll
        for (int k = 0; k < 16; k++) {
            ulonglong2 a01 = *(const ulonglong2*)&sm.g.Ad[k][ty * 8];
            ulonglong2 a23 = *(const ulonglong2*)&sm.g.Ad[k][ty * 8 + 4];
            ulonglong2 b01 = *(const ulonglong2*)&sm.g.Bs[k][tx * 8];
            ulonglong2 b23 = *(const ulonglong2*)&sm.g.Bs[k][tx * 8 + 4];
            u64 av[4] = {a01.x, a01.y, a23.x, a23.y};
            u64 bv[4] = {b01.x, b01.y, b23.x, b23.y};
#pragma unroll
            for (int i = 0; i < 4; i++)
#pragma unroll
                for (int j = 0; j < 4; j++) fma2(acc[i][j], av[i], bv[j]);
        }
        __syncthreads();
    }

    // unpack accumulators into Zt (overlays Ad/Bs; safe after last sync)
#pragma unroll
    for (int i = 0; i < 4; i++) {
        int row = ty * 4 + i;
        float2 c0 = u2f2(acc[i][0]);
        float2 c1 = u2f2(acc[i][1]);
        float2 c2 = u2f2(acc[i][2]);
        float2 c3 = u2f2(acc[i][3]);
        *(float4*)&sm.Zt[row][tx * 8]     = make_float4(c0.x, c0.y, c1.x, c1.y);
        *(float4*)&sm.Zt[row][tx * 8 + 4] = make_float4(c2.x, c2.y, c3.x, c3.y);
    }
    __syncthreads();

    // epilogue: 2048 (b,j) pairs / 256 threads = 8 each
#pragma unroll
    for (int q = 0; q < 8; q++) {
        int p  = tid + 256 * q;
        int bl = p >> 5;
        int j  = p & 31;
        int b  = b0 + bl;
        int n  = n0 + j;
        int tv = tok[(size_t)b * tokStride];
        const float* tr = xW + (size_t)tv * FH;
        float zi = sm.Zt[bl][j]      + tr[n];
        float zf = sm.Zt[bl][32 + j] + tr[HH + n];
        float zg = sm.Zt[bl][64 + j] + tr[2 * HH + n];
        float zo = sm.Zt[bl][96 + j] + tr[3 * HH + n];
        float iv = sigm(zi);
        float fv = sigm(zf);
        float gv = tanhf(zg);
        float ov = sigm(zo);
        size_t idx = (size_t)b * HH + n;
        float cp = c_in[idx];
        float c2 = fv * cp + iv * gv;
        float h2 = ov * tanhf(c2);
        if (tv != 0) { h_out[idx] = h2; c_out[idx] = c2; }
        else         { h_out[idx] = h_in[idx]; c_out[idx] = cp; }
    }
}

// ---------------- decoder output: logits -> softmax -> argmax -> next tok --
// grid 64 blocks (4 batch rows each), 512 threads = (r:4, ks:4, vq:32).
__global__ void __launch_bounds__(512) dec_out_kernel(
    int hping, const float* __restrict__ Wo, const float* __restrict__ bo,
    float* __restrict__ yout, int l, int tokOutPing, int writeToks)
{
    const float* h = g_h[hping];
    __shared__ float hs[4 * HH];          // 16 KB
    __shared__ float ps[4 * VV * 4];      // partials, 8 KB
    __shared__ float wred[16];
    __shared__ float wsum[16];
    __shared__ float wav[16];
    __shared__ int   wai[16];

    const int tid = threadIdx.x;
    const int b0  = blockIdx.x * 4;

    // load 4 h rows (contiguous 4096 floats)
    const float4* hsrc = (const float4*)(h + (size_t)b0 * HH);
    float4* hdst = (float4*)hs;
    for (int i = tid; i < 1024; i += 512) hdst[i] = hsrc[i];
    __syncthreads();

    const int vq = tid & 31;
    const int ks = (tid >> 5) & 3;
    const int r  = tid >> 7;

    const float4* W4 = (const float4*)Wo;  // [k][32] float4s per row
    float a0 = 0.f, a1 = 0.f, a2 = 0.f, a3 = 0.f;
    const float* hr = hs + r * HH;
    const int kbeg = ks * 256;
#pragma unroll 4
    for (int k = kbeg; k < kbeg + 256; k++) {
        float4 w = W4[k * 32 + vq];
        float hv = hr[k];
        a0 = fmaf(hv, w.x, a0);
        a1 = fmaf(hv, w.y, a1);
        a2 = fmaf(hv, w.z, a2);
        a3 = fmaf(hv, w.w, a3);
    }
    const int vb = vq * 4;
    ps[(r * VV + vb + 0) * 4 + ks] = a0;
    ps[(r * VV + vb + 1) * 4 + ks] = a1;
    ps[(r * VV + vb + 2) * 4 + ks] = a2;
    ps[(r * VV + vb + 3) * 4 + ks] = a3;
    __syncthreads();

    const int v  = tid & 127;
    const int r2 = tid >> 7;
    const float* pp = ps + (r2 * VV + v) * 4;
    float lgt = bo[v] + pp[0] + pp[1] + pp[2] + pp[3];

    const int warp = tid >> 5, lane = tid & 31;

    // row max (4 warps per row)
    float m = lgt;
#pragma unroll
    for (int o = 16; o; o >>= 1) m = fmaxf(m, __shfl_xor_sync(0xffffffffu, m, o));
    if (lane == 0) wred[warp] = m;
    __syncthreads();
    float rmax = fmaxf(fmaxf(wred[r2 * 4 + 0], wred[r2 * 4 + 1]),
                       fmaxf(wred[r2 * 4 + 2], wred[r2 * 4 + 3]));
    float e = expf(lgt - rmax);
    float s = e;
#pragma unroll
    for (int o = 16; o; o >>= 1) s += __shfl_xor_sync(0xffffffffu, s, o);
    if (lane == 0) wsum[warp] = s;

    // argmax (ties -> lowest index, matching jnp.argmax)
    float bv = lgt; int bi = v;
#pragma unroll
    for (int o = 16; o; o >>= 1) {
        float ov = __shfl_xor_sync(0xffffffffu, bv, o);
        int   oi = __shfl_xor_sync(0xffffffffu, bi, o);
        if (ov > bv || (ov == bv && oi < bi)) { bv = ov; bi = oi; }
    }
    if (lane == 0) { wav[warp] = bv; wai[warp] = bi; }
    __syncthreads();

    float rsum = wsum[r2 * 4 + 0] + wsum[r2 * 4 + 1] + wsum[r2 * 4 + 2] + wsum[r2 * 4 + 3];
    yout[(size_t)(b0 + r2) * (LL * VV) + (size_t)l * VV + v] = e / rsum;

    if (v == 0) {
        float best = wav[r2 * 4]; int besti = wai[r2 * 4];
#pragma unroll
        for (int w = 1; w < 4; w++) {
            float cv = wav[r2 * 4 + w]; int ci = wai[r2 * 4 + w];
            if (cv > best || (cv == best && ci < besti)) { best = cv; besti = ci; }
        }
        g_tok[tokOutPing][b0 + r2] = besti;
        if (writeToks)
            yout[(size_t)NB * LL * VV + (size_t)l * NB + (b0 + r2)] = (float)besti;
    }
}

// ---------------- host launcher --------------------------------------------
extern "C" void kernel_launch(void* const* d_in, const int* in_sizes, int n_in,
                              void* d_out, int out_size)
{
    // metadata order: inputs, [max_len], enc_emb, enc_W, enc_U, enc_b,
    //                 dec_emb, dec_W, dec_U, dec_b, out_W, out_b
    int o = (n_in > 1 && in_sizes[1] == 1) ? 1 : 0;
    const int*   inputs  = (const int*)  d_in[0];
    const float* enc_emb = (const float*)d_in[1 + o];
    const float* enc_W   = (const float*)d_in[2 + o];
    const float* enc_U   = (const float*)d_in[3 + o];
    const float* enc_b   = (const float*)d_in[4 + o];
    const float* dec_emb = (const float*)d_in[5 + o];
    const float* dec_W   = (const float*)d_in[6 + o];
    const float* dec_U   = (const float*)d_in[7 + o];
    const float* dec_b   = (const float*)d_in[8 + o];
    const float* out_W   = (const float*)d_in[9 + o];
    const float* out_b   = (const float*)d_in[10 + o];
    float* out = (float*)d_out;
    int writeToks = (out_size >= NB * LL * VV + LL * NB) ? 1 : 0;

    init_kernel<<<(NB * HH + 255) / 256, 256>>>();
    table_kernel<<<dim3(FH / 128, 2, 2), 128>>>(enc_emb, enc_W, enc_b,
                                                dec_emb, dec_W, dec_b);
    // encoder: token for row b at step t is inputs[b*TT + t]
    for (int t = 0; t < TT; t++) {
        lstm_step_kernel<<<dim3(HH / 32, NB / 64), 256>>>(
            enc_U, 0, inputs + t, TT, t & 1, (t + 1) & 1, 0);
    }
    // decoder: encoder final state landed in buffer (TT & 1) == 0
    for (int d = 0; d < LL; d++) {
        lstm_step_kernel<<<dim3(HH / 32, NB / 64), 256>>>(
            dec_U, 1, nullptr, 1, d & 1, (d + 1) & 1, d & 1);
        dec_out_kernel<<<64, 512>>>((d + 1) & 1, out_W, out_b, out, d,
                                    (d + 1) & 1, writeToks);
    }
}

// round 5
// speedup vs baseline: 1.3397x; 1.3397x over previous
#include <cuda_runtime.h>
#include <math.h>

#define NB 256   // batch
#define TT 64    // encoder time steps
#define HH 1024  // hidden
#define FH 4096  // 4*hidden
#define VV 128   // vocab
#define LL 32    // decode steps

typedef unsigned long long u64;

// ---------------- scratch (static device globals; no runtime allocation) ----
__device__ float g_encXW[VV * FH];   // enc_emb @ enc_W + enc_b
__device__ float g_decXW[VV * FH];   // dec_emb @ dec_W + dec_b
__device__ float g_h[2][NB * HH];
__device__ float g_c[2][NB * HH];
__device__ int   g_tok[2][NB];

__device__ __forceinline__ float sigm(float x) { return 1.0f / (1.0f + expf(-x)); }

// packed fp32 FMA: d = a*b + d elementwise on two packed f32 (Blackwell FFMA2)
__device__ __forceinline__ void fma2(u64 &d, const u64 a, const u64 b) {
    asm("fma.rn.f32x2 %0, %1, %2, %0;" : "+l"(d) : "l"(a), "l"(b));
}
// broadcast one f32 into both halves of a packed f32x2
__device__ __forceinline__ u64 dup2(float x) {
    u64 r;
    asm("mov.b64 %0, {%1, %1};" : "=l"(r) : "f"(x));
    return r;
}
__device__ __forceinline__ float2 u2f2(u64 v) {
    float2 r;
    asm("mov.b64 {%0, %1}, %2;" : "=f"(r.x), "=f"(r.y) : "l"(v));
    return r;
}

// ---------------- init: zero h0/c0, tok0 = delimiter -----------------------
__global__ void init_kernel() {
    int idx = blockIdx.x * blockDim.x + threadIdx.x;
    if (idx < NB * HH) { g_h[0][idx] = 0.0f; g_c[0][idx] = 0.0f; }
    if (idx < NB)      { g_tok[0][idx] = VV - 1; }
}

// ---------------- table precompute: tab[v][n] = emb[v,:] @ W[:,n] + b[n] ----
// grid (FH/128, 128/64, 2), 128 threads. BM=64, BN=128, BK=16, TM=TN=8.
__global__ void __launch_bounds__(128) table_kernel(
    const float* __restrict__ eemb, const float* __restrict__ eW, const float* __restrict__ eb,
    const float* __restrict__ demb, const float* __restrict__ dW, const float* __restrict__ db)
{
    const float* A; const float* W; const float* bias; float* out;
    if (blockIdx.z == 0) { A = eemb; W = eW; bias = eb; out = g_encXW; }
    else                 { A = demb; W = dW; bias = db; out = g_decXW; }

    __shared__ float As[16][64];
    __shared__ float Bs[16][128];

    const int n0 = blockIdx.x * 128;
    const int m0 = blockIdx.y * 64;
    const int tid = threadIdx.x;

    const int am = tid >> 1, ak = (tid & 1) * 8;     // A: 64x16, 8 floats/thread
    const int bk = tid >> 3, bc = (tid & 7) * 16;    // B: 16x128, 16 floats/thread
    const int ty = tid >> 4, tx = tid & 15;

    float acc[8][8];
#pragma unroll
    for (int i = 0; i < 8; i++)
#pragma unroll
        for (int j = 0; j < 8; j++) acc[i][j] = 0.0f;

    const float* Ap = A + (size_t)(m0 + am) * HH + ak;
    const float* Bp = W + (size_t)bk * FH + n0 + bc;

    float4 ap0 = *(const float4*)(Ap);
    float4 ap1 = *(const float4*)(Ap + 4);
    float4 bp0 = *(const float4*)(Bp);
    float4 bp1 = *(const float4*)(Bp + 4);
    float4 bp2 = *(const float4*)(Bp + 8);
    float4 bp3 = *(const float4*)(Bp + 12);

    const int NKT = HH / 16;
    for (int kt = 0; kt < NKT; ++kt) {
        As[ak + 0][am] = ap0.x; As[ak + 1][am] = ap0.y; As[ak + 2][am] = ap0.z; As[ak + 3][am] = ap0.w;
        As[ak + 4][am] = ap1.x; As[ak + 5][am] = ap1.y; As[ak + 6][am] = ap1.z; As[ak + 7][am] = ap1.w;
        *(float4*)&Bs[bk][bc]      = bp0;
        *(float4*)&Bs[bk][bc + 4]  = bp1;
        *(float4*)&Bs[bk][bc + 8]  = bp2;
        *(float4*)&Bs[bk][bc + 12] = bp3;
        __syncthreads();
        if (kt + 1 < NKT) {
            const float* a2 = Ap + (kt + 1) * 16;
            const float* b2 = Bp + (size_t)(kt + 1) * 16 * FH;
            ap0 = *(const float4*)a2; ap1 = *(const float4*)(a2 + 4);
            bp0 = *(const float4*)b2; bp1 = *(const float4*)(b2 + 4);
            bp2 = *(const float4*)(b2 + 8); bp3 = *(const float4*)(b2 + 12);
        }
#pragma unroll
        for (int k = 0; k < 16; k++) {
            float4 av0 = *(const float4*)&As[k][ty * 8];
            float4 av1 = *(const float4*)&As[k][ty * 8 + 4];
            float4 bv0 = *(const float4*)&Bs[k][tx * 8];
            float4 bv1 = *(const float4*)&Bs[k][tx * 8 + 4];
            float a[8] = {av0.x, av0.y, av0.z, av0.w, av1.x, av1.y, av1.z, av1.w};
            float b[8] = {bv0.x, bv0.y, bv0.z, bv0.w, bv1.x, bv1.y, bv1.z, bv1.w};
#pragma unroll
            for (int i = 0; i < 8; i++)
#pragma unroll
                for (int j = 0; j < 8; j++) acc[i][j] = fmaf(a[i], b[j], acc[i][j]);
        }
        __syncthreads();
    }
#pragma unroll
    for (int i = 0; i < 8; i++) {
        int m = m0 + ty * 8 + i;
#pragma unroll
        for (int j = 0; j < 8; j++) {
            int n = n0 + tx * 8 + j;
            out[(size_t)m * FH + n] = acc[i][j] + bias[n];
        }
    }
}

// ---------------- fused LSTM step (FFMA2, N-packed accumulators) -----------
// z = xW[tok] + h_in @ U ; gates ; masked h/c update.
// Block: 64(batch) x 32(col-per-gate) tile, all 4 gates = 128 internal cols.
// 128 threads, thread tile 8m x 8n (held as 8x4 packed f32x2 accumulators).
// A read as scalars + register-broadcast (mov.b64 {a,a}); B read as u64 pairs
// straight from the same Bs layout as the fp32 kernel. Same smem traffic as
// R1, half the FMA-pipe instructions.
// grid (HH/32=32, NB/64=4) = 128 blocks.
__global__ void __launch_bounds__(128) lstm_step_kernel(
    const float* __restrict__ U, int isDec,
    const int* __restrict__ tokExt, int tokStride,
    int pin, int pout, int tokPing)
{
    const float* xW   = isDec ? g_decXW : g_encXW;
    const int*   tok  = isDec ? g_tok[tokPing] : tokExt;
    const float* h_in = g_h[pin];
    const float* c_in = g_c[pin];
    float* h_out = g_h[pout];
    float* c_out = g_c[pout];

    __shared__ union {
        struct { float As[16][64]; float Bs[16][128]; } g;  // 12 KB during GEMM
        float Zt[64][128];                                   // 32 KB after
    } sm;

    const int n0 = blockIdx.x * 32;
    const int b0 = blockIdx.y * 64;
    const int tid = threadIdx.x;

    const int am = tid >> 1, ak = (tid & 1) * 8;    // A: 64x16, 8 floats/thread
    const int bk = tid >> 3, bc = (tid & 7) * 16;   // B: 16x128, 16 floats/thread
    const int ty = tid >> 4, tx = tid & 15;         // compute: 8m x 8n

    u64 acc[8][4];
#pragma unroll
    for (int i = 0; i < 8; i++)
#pragma unroll
        for (int j = 0; j < 4; j++) acc[i][j] = 0ULL;

    const int bgate = bc >> 5;
    const int bj    = bc & 31;
    const float* Ap = h_in + (size_t)(b0 + am) * HH + ak;
    const float* Bp = U + (size_t)bk * FH + (size_t)bgate * HH + n0 + bj;

    float4 ap0 = *(const float4*)(Ap);
    float4 ap1 = *(const float4*)(Ap + 4);
    float4 bp0 = *(const float4*)(Bp);
    float4 bp1 = *(const float4*)(Bp + 4);
    float4 bp2 = *(const float4*)(Bp + 8);
    float4 bp3 = *(const float4*)(Bp + 12);

    const int NKT = HH / 16;
    for (int kt = 0; kt < NKT; ++kt) {
        sm.g.As[ak + 0][am] = ap0.x; sm.g.As[ak + 1][am] = ap0.y;
        sm.g.As[ak + 2][am] = ap0.z; sm.g.As[ak + 3][am] = ap0.w;
        sm.g.As[ak + 4][am] = ap1.x; sm.g.As[ak + 5][am] = ap1.y;
        sm.g.As[ak + 6][am] = ap1.z; sm.g.As[ak + 7][am] = ap1.w;
        *(float4*)&sm.g.Bs[bk][bc]      = bp0;
        *(float4*)&sm.g.Bs[bk][bc + 4]  = bp1;
        *(float4*)&sm.g.Bs[bk][bc + 8]  = bp2;
        *(float4*)&sm.g.Bs[bk][bc + 12] = bp3;
        __syncthreads();
        if (kt + 1 < NKT) {
            const float* a2 = Ap + (kt + 1) * 16;
            const float* b2 = Bp + (size_t)(kt + 1) * 16 * FH;
            ap0 = *(const float4*)a2; ap1 = *(const float4*)(a2 + 4);
            bp0 = *(const float4*)b2; bp1 = *(const float4*)(b2 + 4);
            bp2 = *(const float4*)(b2 + 8); bp3 = *(const float4*)(b2 + 12);
        }
#pragma unroll
        for (int k = 0; k < 16; k++) {
            float4 av0 = *(const float4*)&sm.g.As[k][ty * 8];
            float4 av1 = *(const float4*)&sm.g.As[k][ty * 8 + 4];
            ulonglong2 b01 = *(const ulonglong2*)&sm.g.Bs[k][tx * 8];
            ulonglong2 b23 = *(const ulonglong2*)&sm.g.Bs[k][tx * 8 + 4];
            u64 ad[8];
            ad[0] = dup2(av0.x); ad[1] = dup2(av0.y);
            ad[2] = dup2(av0.z); ad[3] = dup2(av0.w);
            ad[4] = dup2(av1.x); ad[5] = dup2(av1.y);
            ad[6] = dup2(av1.z); ad[7] = dup2(av1.w);
            u64 bv[4] = {b01.x, b01.y, b23.x, b23.y};
#pragma unroll
            for (int i = 0; i < 8; i++)
#pragma unroll
                for (int j = 0; j < 4; j++) fma2(acc[i][j], ad[i], bv[j]);
        }
        __syncthreads();
    }

    // unpack accumulators into Zt (overlays As/Bs; safe after last sync)
#pragma unroll
    for (int i = 0; i < 8; i++) {
        int row = ty * 8 + i;
        float2 c0 = u2f2(acc[i][0]);
        float2 c1 = u2f2(acc[i][1]);
        float2 c2 = u2f2(acc[i][2]);
        float2 c3 = u2f2(acc[i][3]);
        *(float4*)&sm.Zt[row][tx * 8]     = make_float4(c0.x, c0.y, c1.x, c1.y);
        *(float4*)&sm.Zt[row][tx * 8 + 4] = make_float4(c2.x, c2.y, c3.x, c3.y);
    }
    __syncthreads();

    // epilogue: 2048 (b,j) pairs / 128 threads = 16 each
#pragma unroll 4
    for (int q = 0; q < 16; q++) {
        int p  = tid * 16 + q;
        int bl = p >> 5;
        int j  = p & 31;
        int b  = b0 + bl;
        int n  = n0 + j;
        int tv = tok[(size_t)b * tokStride];
        const float* tr = xW + (size_t)tv * FH;
        float zi = sm.Zt[bl][j]      + tr[n];
        float zf = sm.Zt[bl][32 + j] + tr[HH + n];
        float zg = sm.Zt[bl][64 + j] + tr[2 * HH + n];
        float zo = sm.Zt[bl][96 + j] + tr[3 * HH + n];
        float iv = sigm(zi);
        float fv = sigm(zf);
        float gv = tanhf(zg);
        float ov = sigm(zo);
        size_t idx = (size_t)b * HH + n;
        float cp = c_in[idx];
        float c2 = fv * cp + iv * gv;
        float h2 = ov * tanhf(c2);
        if (tv != 0) { h_out[idx] = h2; c_out[idx] = c2; }
        else         { h_out[idx] = h_in[idx]; c_out[idx] = cp; }
    }
}

// ---------------- decoder output: logits -> softmax -> argmax -> next tok --
// grid 64 blocks (4 batch rows each), 512 threads = (r:4, ks:4, vq:32).
__global__ void __launch_bounds__(512) dec_out_kernel(
    int hping, const float* __restrict__ Wo, const float* __restrict__ bo,
    float* __restrict__ yout, int l, int tokOutPing, int writeToks)
{
    const float* h = g_h[hping];
    __shared__ float hs[4 * HH];          // 16 KB
    __shared__ float ps[4 * VV * 4];      // partials, 8 KB
    __shared__ float wred[16];
    __shared__ float wsum[16];
    __shared__ float wav[16];
    __shared__ int   wai[16];

    const int tid = threadIdx.x;
    const int b0  = blockIdx.x * 4;

    // load 4 h rows (contiguous 4096 floats)
    const float4* hsrc = (const float4*)(h + (size_t)b0 * HH);
    float4* hdst = (float4*)hs;
    for (int i = tid; i < 1024; i += 512) hdst[i] = hsrc[i];
    __syncthreads();

    const int vq = tid & 31;
    const int ks = (tid >> 5) & 3;
    const int r  = tid >> 7;

    const float4* W4 = (const float4*)Wo;  // [k][32] float4s per row
    float a0 = 0.f, a1 = 0.f, a2 = 0.f, a3 = 0.f;
    const float* hr = hs + r * HH;
    const int kbeg = ks * 256;
#pragma unroll 4
    for (int k = kbeg; k < kbeg + 256; k++) {
        float4 w = W4[k * 32 + vq];
        float hv = hr[k];
        a0 = fmaf(hv, w.x, a0);
        a1 = fmaf(hv, w.y, a1);
        a2 = fmaf(hv, w.z, a2);
        a3 = fmaf(hv, w.w, a3);
    }
    const int vb = vq * 4;
    ps[(r * VV + vb + 0) * 4 + ks] = a0;
    ps[(r * VV + vb + 1) * 4 + ks] = a1;
    ps[(r * VV + vb + 2) * 4 + ks] = a2;
    ps[(r * VV + vb + 3) * 4 + ks] = a3;
    __syncthreads();

    const int v  = tid & 127;
    const int r2 = tid >> 7;
    const float* pp = ps + (r2 * VV + v) * 4;
    float lgt = bo[v] + pp[0] + pp[1] + pp[2] + pp[3];

    const int warp = tid >> 5, lane = tid & 31;

    // row max (4 warps per row)
    float m = lgt;
#pragma unroll
    for (int o = 16; o; o >>= 1) m = fmaxf(m, __shfl_xor_sync(0xffffffffu, m, o));
    if (lane == 0) wred[warp] = m;
    __syncthreads();
    float rmax = fmaxf(fmaxf(wred[r2 * 4 + 0], wred[r2 * 4 + 1]),
                       fmaxf(wred[r2 * 4 + 2], wred[r2 * 4 + 3]));
    float e = expf(lgt - rmax);
    float s = e;
#pragma unroll
    for (int o = 16; o; o >>= 1) s += __shfl_xor_sync(0xffffffffu, s, o);
    if (lane == 0) wsum[warp] = s;

    // argmax (ties -> lowest index, matching jnp.argmax)
    float bv = lgt; int bi = v;
#pragma unroll
    for (int o = 16; o; o >>= 1) {
        float ov = __shfl_xor_sync(0xffffffffu, bv, o);
        int   oi = __shfl_xor_sync(0xffffffffu, bi, o);
        if (ov > bv || (ov == bv && oi < bi)) { bv = ov; bi = oi; }
    }
    if (lane == 0) { wav[warp] = bv; wai[warp] = bi; }
    __syncthreads();

    float rsum = wsum[r2 * 4 + 0] + wsum[r2 * 4 + 1] + wsum[r2 * 4 + 2] + wsum[r2 * 4 + 3];
    yout[(size_t)(b0 + r2) * (LL * VV) + (size_t)l * VV + v] = e / rsum;

    if (v == 0) {
        float best = wav[r2 * 4]; int besti = wai[r2 * 4];
#pragma unroll
        for (int w = 1; w < 4; w++) {
            float cv = wav[r2 * 4 + w]; int ci = wai[r2 * 4 + w];
            if (cv > best || (cv == best && ci < besti)) { best = cv; besti = ci; }
        }
        g_tok[tokOutPing][b0 + r2] = besti;
        if (writeToks)
            yout[(size_t)NB * LL * VV + (size_t)l * NB + (b0 + r2)] = (float)besti;
    }
}

// ---------------- host launcher --------------------------------------------
extern "C" void kernel_launch(void* const* d_in, const int* in_sizes, int n_in,
                              void* d_out, int out_size)
{
    // metadata order: inputs, [max_len], enc_emb, enc_W, enc_U, enc_b,
    //                 dec_emb, dec_W, dec_U, dec_b, out_W, out_b
    int o = (n_in > 1 && in_sizes[1] == 1) ? 1 : 0;
    const int*   inputs  = (const int*)  d_in[0];
    const float* enc_emb = (const float*)d_in[1 + o];
    const float* enc_W   = (const float*)d_in[2 + o];
    const float* enc_U   = (const float*)d_in[3 + o];
    const float* enc_b   = (const float*)d_in[4 + o];
    const float* dec_emb = (const float*)d_in[5 + o];
    const float* dec_W   = (const float*)d_in[6 + o];
    const float* dec_U   = (const float*)d_in[7 + o];
    const float* dec_b   = (const float*)d_in[8 + o];
    const float* out_W   = (const float*)d_in[9 + o];
    const float* out_b   = (const float*)d_in[10 + o];
    float* out = (float*)d_out;
    int writeToks = (out_size >= NB * LL * VV + LL * NB) ? 1 : 0;

    init_kernel<<<(NB * HH + 255) / 256, 256>>>();
    table_kernel<<<dim3(FH / 128, 2, 2), 128>>>(enc_emb, enc_W, enc_b,
                                                dec_emb, dec_W, dec_b);
    // encoder: token for row b at step t is inputs[b*TT + t]
    for (int t = 0; t < TT; t++) {
        lstm_step_kernel<<<dim3(HH / 32, NB / 64), 128>>>(
            enc_U, 0, inputs + t, TT, t & 1, (t + 1) & 1, 0);
    }
    // decoder: encoder final state landed in buffer (TT & 1) == 0
    for (int d = 0; d < LL; d++) {
        lstm_step_kernel<<<dim3(HH / 32, NB / 64), 128>>>(
            dec_U, 1, nullptr, 1, d & 1, (d + 1) & 1, d & 1);
        dec_out_kernel<<<64, 512>>>((d + 1) & 1, out_W, out_b, out, d,
                                    (d + 1) & 1, writeToks);
    }
}